// round 13
// baseline (speedup 1.0000x reference)
#include <cuda_runtime.h>
#include <cstdint>

// ---------------- problem constants ----------------
#define BB   16
#define DD   512
#define TT   2048
#define KK   1024
#define NN   (BB*TT)          // 32768
#define NQ   (BB*DD*TT)       // 16777216

// ---------------- pass-1 tiling ----------------
#define M_TILE   256
#define N_TILE   64
#define NT_COUNT (KK / N_TILE)        // 16
#define D_STAGE  64
#define STAGES_PER_NT (DD / D_STAGE)  // 8
#define TOT_STAGES (NT_COUNT * STAGES_PER_NT)  // 128
#define THREADS  512

// smem strides (floats). A [d][m] stride 260: bank = 4q + r4 (distinct).
// B [n][d] stride 68: bank = 4r4 + q (distinct).
#define A_LD 260
#define B_LD 68
#define A_PLANE (D_STAGE * A_LD * 4)   // 66560
#define B_PLANE (N_TILE * B_LD * 4)    // 17408
#define OFF_B   A_PLANE
#define BUF_BYTES (A_PLANE + B_PLANE)  // 83968
#define DYN_SMEM  (2 * BUF_BYTES)      // 167936

typedef unsigned long long ull;

// ---------------- PTX helpers (arch-neutral: compute_80+) ----------------
__device__ __forceinline__ uint32_t smem_u32(const void* p) {
    uint32_t a;
    asm("{ .reg .u64 t; cvta.to.shared.u64 t, %1; cvt.u32.u64 %0, t; }" : "=r"(a) : "l"(p));
    return a;
}
#define CP_ASYNC16(dst, src) asm volatile("cp.async.cg.shared.global [%0], [%1], 16;" :: "r"(dst), "l"(src))
#define CP_COMMIT()          asm volatile("cp.async.commit_group;" ::: "memory")
#define CP_WAIT1()           asm volatile("cp.async.wait_group 1;" ::: "memory")
#define CP_WAIT0()           asm volatile("cp.async.wait_group 0;" ::: "memory")

__device__ __forceinline__ uint32_t to_tf32(float v) {
    uint32_t r;
    asm("cvt.rna.tf32.f32 %0, %1;" : "=r"(r) : "f"(v));
    return r;
}
#define MMA_TF32(c0,c1,c2,c3, a0,a1,a2,a3, b0,b1) \
    asm volatile("mma.sync.aligned.m16n8k8.row.col.f32.tf32.tf32.f32 " \
        "{%0,%1,%2,%3}, {%4,%5,%6,%7}, {%8,%9}, {%0,%1,%2,%3};" \
        : "+f"(c0), "+f"(c1), "+f"(c2), "+f"(c3) \
        : "r"(a0), "r"(a1), "r"(a2), "r"(a3), "r"(b0), "r"(b1))

// ---------------- device scratch (static: allocation-free rule) ---------------
__device__ float  g_zHi[(size_t)NQ];       // 64 MB: tf32-hi of z, [b][d][t]
__device__ float  g_zT[(size_t)NQ];        // 64 MB: exact fp32 z, [n][d]
__device__ float  g_dist[(size_t)NN*KK];   // 128 MB: approx dists
__device__ float  g_cbHi[KK * DD];         // 2 MB: tf32-hi codebook [k][d]
__device__ float  g_cbT[DD * KK];          // gather cache [d][k]
__device__ float  g_wsq[KK];
__device__ float  g_zsq[NN];
__device__ int    g_idx[NN];
__device__ int    g_wsqmax_bits;           // max wsq (float bits; atomicMax idempotent)
__device__ double g_loss;

// ---------------- K0a: codebook prep ------------------------------------------
__global__ void prep_codebook(const float* __restrict__ cb) {
    int k   = blockIdx.x;
    int tid = threadIdx.x;      // 128
    float s = 0.f;
    for (int d = tid; d < DD; d += 128) {
        float v = cb[(size_t)k * DD + d];
        g_cbT[(size_t)d * KK + k]  = v;
        g_cbHi[(size_t)k * DD + d] = __uint_as_float(to_tf32(v));
        s += v * v;
    }
    #pragma unroll
    for (int o = 16; o; o >>= 1) s += __shfl_xor_sync(0xffffffffu, s, o);
    __shared__ float ws[4];
    if ((tid & 31) == 0) ws[tid >> 5] = s;
    __syncthreads();
    if (tid == 0) {
        float w = (ws[0] + ws[1]) + (ws[2] + ws[3]);
        g_wsq[k] = w;
        atomicMax(&g_wsqmax_bits, __float_as_int(w));
        if (k == 0) g_loss = 0.0;
    }
}

// ---------------- K0b: z -> hi plane ([b][d][t]) + exact transposed ([n][d]) --
__global__ void transpose_split(const float* __restrict__ z) {
    __shared__ float tile[32][33];
    int b  = blockIdx.z;
    int d0 = blockIdx.y * 32;
    int t0 = blockIdx.x * 32;
    int tx = threadIdx.x, ty = threadIdx.y;
    #pragma unroll
    for (int i = ty; i < 32; i += 8) {
        size_t off = ((size_t)b * DD + d0 + i) * TT + t0 + tx;
        float v = z[off];
        g_zHi[off] = __uint_as_float(to_tf32(v));
        tile[i][tx] = v;
    }
    __syncthreads();
    #pragma unroll
    for (int i = ty; i < 32; i += 8)
        g_zT[(size_t)(b * TT + t0 + i) * DD + d0 + tx] = tile[tx][i];
}

// ---------------- K0c: per-row |z|^2 ------------------------------------------
__global__ void compute_zsq(const float* __restrict__ z) {
    int n0 = blockIdx.x * 128;
    int b  = n0 >> 11;
    int t  = (n0 & (TT - 1)) + threadIdx.x;
    const float* zb = z + (size_t)b * DD * TT + t;
    float s0 = 0.f, s1 = 0.f, s2 = 0.f, s3 = 0.f;
    #pragma unroll 4
    for (int d = 0; d < DD; d += 4) {
        float v0 = zb[(size_t)(d + 0) * TT];
        float v1 = zb[(size_t)(d + 1) * TT];
        float v2 = zb[(size_t)(d + 2) * TT];
        float v3 = zb[(size_t)(d + 3) * TT];
        s0 = fmaf(v0, v0, s0);
        s1 = fmaf(v1, v1, s1);
        s2 = fmaf(v2, v2, s2);
        s3 = fmaf(v3, v3, s3);
    }
    g_zsq[n0 + threadIdx.x] = (s0 + s1) + (s2 + s3);
}

// ---------------- K1: pass-1 TF32 hi-only GEMM -> dist matrix -----------------
__global__ __launch_bounds__(THREADS)
void vq_pass1()
{
    extern __shared__ char dyn[];
    __shared__ float sWsq[KK];

    const uint32_t dynb = smem_u32(dyn);
    int tid  = threadIdx.x;
    int lane = tid & 31;
    int wid  = tid >> 5;
    int q    = lane & 3;
    int r4   = lane >> 2;
    int warpM  = (wid & 7) * 32;   // 8 M-bands of 32
    int warpNb = wid >> 3;         // 2 N-bands
    int warpN  = warpNb * 32;

    int n0 = blockIdx.x * M_TILE;  // grid = 128
    int b  = n0 >> 11;
    int t0 = n0 & (TT - 1);
    size_t zoff = (size_t)b * DD * TT + t0;

    sWsq[tid]       = g_wsq[tid];
    sWsq[tid + 512] = g_wsq[tid + 512];

    float zsqr[4];   // rows warpM + 16mi + 8h + r4
    #pragma unroll
    for (int mi = 0; mi < 2; mi++)
        #pragma unroll
        for (int h = 0; h < 2; h++)
            zsqr[mi * 2 + h] = g_zsq[n0 + warpM + 16 * mi + 8 * h + r4];

    float acc[2][4][4];   // (mi, nf, e) = 32 floats
    #pragma unroll
    for (int mi = 0; mi < 2; mi++)
        #pragma unroll
        for (int nf = 0; nf < 4; nf++)
            #pragma unroll
            for (int e = 0; e < 4; e++) acc[mi][nf][e] = 0.f;

    // cp.async decomposition: A 4096 x16B chunks (8/thread), B 1024 (2/thread)
    int aRow[8], aC[8], bN[2], bCd[2];
    #pragma unroll
    for (int i = 0; i < 8; i++) {
        int u = tid + i * 512;
        aRow[i] = u >> 6;          // 0..63  (d row)
        aC[i]   = u & 63;          // 16B chunk along m
    }
    #pragma unroll
    for (int i = 0; i < 2; i++) {
        int u = tid + i * 512;
        bN[i]  = u >> 4;           // 0..63 (n row)
        bCd[i] = u & 15;           // 16B chunk along d
    }

    auto load_stage = [&](int gs, int buf) {
        int d0  = (gs & (STAGES_PER_NT - 1)) * D_STAGE;
        int kb0 = (gs >> 3) * N_TILE;
        uint32_t bb = dynb + buf * BUF_BYTES;
        #pragma unroll
        for (int i = 0; i < 8; i++)
            CP_ASYNC16(bb + aRow[i] * (A_LD * 4) + aC[i] * 16,
                       g_zHi + zoff + (size_t)(d0 + aRow[i]) * TT + aC[i] * 4);
        #pragma unroll
        for (int i = 0; i < 2; i++)
            CP_ASYNC16(bb + OFF_B + bN[i] * (B_LD * 4) + bCd[i] * 16,
                       g_cbHi + (size_t)(kb0 + bN[i]) * DD + d0 + bCd[i] * 4);
        CP_COMMIT();
    };

    __syncthreads();   // sWsq ready
    load_stage(0, 0);

    #pragma unroll 1
    for (int gs = 0; gs < TOT_STAGES; gs++) {
        int cur = gs & 1;
        if (gs + 1 < TOT_STAGES) { load_stage(gs + 1, cur ^ 1); CP_WAIT1(); }
        else                     { CP_WAIT0(); }
        __syncthreads();

        const uint32_t* As = (const uint32_t*)(dyn + cur * BUF_BYTES);
        const uint32_t* Bs = (const uint32_t*)(dyn + cur * BUF_BYTES + OFF_B);

        #pragma unroll
        for (int j = 0; j < 8; j++) {
            uint32_t ah[2][4];
            #pragma unroll
            for (int mi = 0; mi < 2; mi++) {
                int rm = warpM + 16 * mi + r4;
                #pragma unroll
                for (int e = 0; e < 4; e++) {
                    int dd = 8 * j + q + (e >> 1) * 4;
                    int mm = rm + (e & 1) * 8;
                    ah[mi][e] = As[dd * A_LD + mm];
                }
            }
            #pragma unroll
            for (int nf = 0; nf < 4; nf++) {
                int nn = warpN + 8 * nf + r4;
                uint32_t b0 = Bs[nn * B_LD + 8 * j + q];
                uint32_t b1 = Bs[nn * B_LD + 8 * j + q + 4];
                #pragma unroll
                for (int mi = 0; mi < 2; mi++) {
                    float* c = acc[mi][nf];
                    MMA_TF32(c[0], c[1], c[2], c[3],
                             ah[mi][0], ah[mi][1], ah[mi][2], ah[mi][3], b0, b1);
                }
            }
        }

        // n-tile boundary: store dists, reset acc
        if ((gs & (STAGES_PER_NT - 1)) == STAGES_PER_NT - 1) {
            int kb0 = (gs >> 3) * N_TILE;
            #pragma unroll
            for (int mi = 0; mi < 2; mi++) {
                #pragma unroll
                for (int h = 0; h < 2; h++) {
                    int n = n0 + warpM + 16 * mi + 8 * h + r4;
                    float zs = zsqr[mi * 2 + h];
                    #pragma unroll
                    for (int nf = 0; nf < 4; nf++) {
                        int col = kb0 + warpN + 8 * nf + 2 * q;
                        float v0 = __fadd_rn(__fsub_rn(zs, __fmul_rn(2.0f, acc[mi][nf][2 * h + 0])), sWsq[col]);
                        float v1 = __fadd_rn(__fsub_rn(zs, __fmul_rn(2.0f, acc[mi][nf][2 * h + 1])), sWsq[col + 1]);
                        *(float2*)(g_dist + (size_t)n * KK + col) = make_float2(v0, v1);
                    }
                }
            }
            #pragma unroll
            for (int mi = 0; mi < 2; mi++)
                #pragma unroll
                for (int nf = 0; nf < 4; nf++)
                    #pragma unroll
                    for (int e = 0; e < 4; e++) acc[mi][nf][e] = 0.f;
        }
        __syncthreads();   // release buf cur
    }
}

// ---------------- K2: refine — exact argmin from candidates -------------------
__global__ __launch_bounds__(128)
void vq_refine(const float* __restrict__ cb, float* __restrict__ out) {
    int n   = blockIdx.x;
    int tid = threadIdx.x;
    int lane = tid & 31, wid = tid >> 5;
    const float* dr = g_dist + (size_t)n * KK;

    float4 da = ((const float4*)dr)[tid * 2];
    float4 db = ((const float4*)dr)[tid * 2 + 1];
    float d8[8] = { da.x, da.y, da.z, da.w, db.x, db.y, db.z, db.w };

    // local packed min (ascending k, strict < -> first index)
    ull best = ~0ull;
    #pragma unroll
    for (int i = 0; i < 8; i++) {
        ull p = ((ull)__float_as_uint(d8[i]) << 32) | (uint32_t)(tid * 8 + i);
        if (p < best) best = p;
    }
    #pragma unroll
    for (int o = 16; o; o >>= 1) {
        ull v = __shfl_xor_sync(0xffffffffu, best, o);
        if (v < best) best = v;
    }
    __shared__ ull sMin[4];
    if (lane == 0) sMin[wid] = best;
    __syncthreads();
    ull m01 = sMin[0] < sMin[1] ? sMin[0] : sMin[1];
    ull m23 = sMin[2] < sMin[3] ? sMin[2] : sMin[3];
    ull gmin = m01 < m23 ? m01 : m23;
    float minv = __uint_as_float((uint32_t)(gmin >> 32));

    float zsq = g_zsq[n];
    float wmaxsq = __int_as_float(g_wsqmax_bits);
    // per-entry bound (inflated): 2.5e-3 * ||z||*||w||max + 5e-4 ; margin = 2*bound
    float bound = fmaf(2.5e-3f, sqrtf(zsq * wmaxsq), 5.0e-4f);
    float thresh = minv + 2.0f * bound;

    __shared__ int sCnt, sOvf;
    __shared__ int sList[32];
    if (tid == 0) { sCnt = 0; sOvf = 0; }
    __syncthreads();
    #pragma unroll
    for (int i = 0; i < 8; i++) {
        if (d8[i] <= thresh) {
            int p = atomicAdd(&sCnt, 1);
            if (p < 32) sList[p] = tid * 8 + i; else sOvf = 1;
        }
    }
    __syncthreads();

    int winner;
    if (sCnt == 1 && !sOvf) {
        winner = (int)(uint32_t)(gmin & 0xffffffffULL);
    } else {
        __shared__ float sP[4];
        __shared__ ull   sBest;
        if (tid == 0) sBest = ~0ull;
        int m = sOvf ? KK : sCnt;
        const float* zr = g_zT + (size_t)n * DD;
        float4 zv0 = ((const float4*)zr)[tid];               // d = 4*tid .. +3
        for (int c = 0; c < m; c++) {
            int k = sOvf ? c : sList[c];
            const float* wr = cb + (size_t)k * DD;
            float4 wv = ((const float4*)wr)[tid];
            float s = 0.f;
            s = fmaf(zv0.x, wv.x, s);
            s = fmaf(zv0.y, wv.y, s);
            s = fmaf(zv0.z, wv.z, s);
            s = fmaf(zv0.w, wv.w, s);
            #pragma unroll
            for (int o = 16; o; o >>= 1) s += __shfl_xor_sync(0xffffffffu, s, o);
            if (lane == 0) sP[wid] = s;
            __syncthreads();
            if (tid == 0) {
                float S = (sP[0] + sP[1]) + (sP[2] + sP[3]);
                float dist = __fadd_rn(__fsub_rn(zsq, __fmul_rn(2.0f, S)), g_wsq[k]);
                ull p = ((ull)__float_as_uint(dist) << 32) | (uint32_t)k;
                if (p < sBest) sBest = p;
            }
            __syncthreads();
        }
        winner = (int)(uint32_t)(sBest & 0xffffffffULL);
    }

    if (tid == 0) {
        g_idx[n] = winner;
        out[(size_t)NQ + n] = (float)winner;
    }
}

// ---------------- K3: gather z_q, write z_q_st, loss (vectorized) -------------
__global__ void gather_out(const float* __restrict__ z, float* __restrict__ out) {
    int bd = blockIdx.x;
    int b  = bd >> 9;
    int d  = bd & (DD - 1);
    __shared__ float row[KK];
    ((float4*)row)[threadIdx.x] = ((const float4*)(g_cbT + (size_t)d * KK))[threadIdx.x];
    __syncthreads();

    size_t base = ((size_t)b * DD + d) * TT;
    int t = threadIdx.x * 8;
    int4  i0 = *(const int4*)(g_idx + b * TT + t);
    int4  i1 = *(const int4*)(g_idx + b * TT + t + 4);
    float4 z0 = *(const float4*)(z + base + t);
    float4 z1 = *(const float4*)(z + base + t + 4);

    float4 o0, o1;
    double lsum = 0.0;
    {
        float zq, df;
        zq = row[i0.x]; o0.x = __fadd_rn(z0.x, __fsub_rn(zq, z0.x)); df = __fsub_rn(zq, z0.x); lsum += (double)df * df;
        zq = row[i0.y]; o0.y = __fadd_rn(z0.y, __fsub_rn(zq, z0.y)); df = __fsub_rn(zq, z0.y); lsum += (double)df * df;
        zq = row[i0.z]; o0.z = __fadd_rn(z0.z, __fsub_rn(zq, z0.z)); df = __fsub_rn(zq, z0.z); lsum += (double)df * df;
        zq = row[i0.w]; o0.w = __fadd_rn(z0.w, __fsub_rn(zq, z0.w)); df = __fsub_rn(zq, z0.w); lsum += (double)df * df;
        zq = row[i1.x]; o1.x = __fadd_rn(z1.x, __fsub_rn(zq, z1.x)); df = __fsub_rn(zq, z1.x); lsum += (double)df * df;
        zq = row[i1.y]; o1.y = __fadd_rn(z1.y, __fsub_rn(zq, z1.y)); df = __fsub_rn(zq, z1.y); lsum += (double)df * df;
        zq = row[i1.z]; o1.z = __fadd_rn(z1.z, __fsub_rn(zq, z1.z)); df = __fsub_rn(zq, z1.z); lsum += (double)df * df;
        zq = row[i1.w]; o1.w = __fadd_rn(z1.w, __fsub_rn(zq, z1.w)); df = __fsub_rn(zq, z1.w); lsum += (double)df * df;
    }
    *(float4*)(out + base + t)     = o0;
    *(float4*)(out + base + t + 4) = o1;

    #pragma unroll
    for (int o = 16; o; o >>= 1) lsum += __shfl_xor_sync(0xffffffffu, lsum, o);
    __shared__ double red[8];
    if ((threadIdx.x & 31) == 0) red[threadIdx.x >> 5] = lsum;
    __syncthreads();
    if (threadIdx.x == 0) {
        double s = 0.0;
        #pragma unroll
        for (int i = 0; i < 8; i++) s += red[i];
        atomicAdd(&g_loss, s);
    }
}

// ---------------- K4: finalize loss ------------------------------------------
__global__ void finalize_loss(float* __restrict__ out) {
    out[(size_t)NQ + NN] = (float)(g_loss * (1.25 / (double)NQ));
}

// ---------------- launch ------------------------------------------------------
extern "C" void kernel_launch(void* const* d_in, const int* in_sizes, int n_in,
                              void* d_out, int out_size) {
    const float* z  = (const float*)d_in[0];   // [16, 512, 2048] fp32
    const float* cb = (const float*)d_in[1];   // [1024, 512] fp32
    float* out = (float*)d_out;                // [z_q_st | indices | loss]

    cudaFuncSetAttribute(vq_pass1, cudaFuncAttributeMaxDynamicSharedMemorySize, DYN_SMEM);

    prep_codebook<<<KK, 128>>>(cb);
    transpose_split<<<dim3(TT / 32, DD / 32, BB), dim3(32, 8)>>>(z);
    compute_zsq<<<NN / 128, 128>>>(z);
    vq_pass1<<<NN / M_TILE, THREADS, DYN_SMEM>>>();
    vq_refine<<<NN, 128>>>(cb, out);
    gather_out<<<BB * DD, 256>>>(z, out);
    finalize_loss<<<1, 1>>>(out);
}

// round 14
// speedup vs baseline: 1.2447x; 1.2447x over previous
#include <cuda_runtime.h>
#include <cstdint>

// ---------------- problem constants ----------------
#define BB   16
#define DD   512
#define TT   2048
#define KK   1024
#define NN   (BB*TT)          // 32768
#define NQ   (BB*DD*TT)       // 16777216

// ---------------- pass-1 tiling (R10-proven skeleton, hi-only) ----------------
#define M_TILE   128
#define N_TILE   128
#define NT_COUNT (KK / N_TILE)        // 8
#define D_STAGE  32
#define STAGES_PER_NT (DD / D_STAGE)  // 16
#define TOT_STAGES (NT_COUNT * STAGES_PER_NT)  // 128
#define THREADS  256

// smem strides (floats):
// A [d][m]: stride 136 -> LDS bank = 8q + r4 (all 32 distinct)
// B [n][d]: stride 36  -> LDS bank = 4r4 + q (all 32 distinct)
#define A_LD 136
#define B_LD 36
#define A_PLANE (D_STAGE * A_LD * 4)   // 17408
#define B_PLANE (N_TILE * B_LD * 4)    // 18432
#define OFF_B   A_PLANE
#define BUF_BYTES (A_PLANE + B_PLANE)  // 35840
#define DYN_SMEM  (2 * BUF_BYTES)      // 71680  -> 2 CTAs/SM, grid 256 = ONE wave

typedef unsigned long long ull;

// ---------------- PTX helpers (arch-neutral: compute_80+) ----------------
__device__ __forceinline__ uint32_t smem_u32(const void* p) {
    uint32_t a;
    asm("{ .reg .u64 t; cvta.to.shared.u64 t, %1; cvt.u32.u64 %0, t; }" : "=r"(a) : "l"(p));
    return a;
}
#define CP_ASYNC16(dst, src) asm volatile("cp.async.cg.shared.global [%0], [%1], 16;" :: "r"(dst), "l"(src))
#define CP_COMMIT()          asm volatile("cp.async.commit_group;" ::: "memory")
#define CP_WAIT1()           asm volatile("cp.async.wait_group 1;" ::: "memory")
#define CP_WAIT0()           asm volatile("cp.async.wait_group 0;" ::: "memory")

__device__ __forceinline__ uint32_t to_tf32(float v) {
    uint32_t r;
    asm("cvt.rna.tf32.f32 %0, %1;" : "=r"(r) : "f"(v));
    return r;
}
#define MMA_TF32(c0,c1,c2,c3, a0,a1,a2,a3, b0,b1) \
    asm volatile("mma.sync.aligned.m16n8k8.row.col.f32.tf32.tf32.f32 " \
        "{%0,%1,%2,%3}, {%4,%5,%6,%7}, {%8,%9}, {%0,%1,%2,%3};" \
        : "+f"(c0), "+f"(c1), "+f"(c2), "+f"(c3) \
        : "r"(a0), "r"(a1), "r"(a2), "r"(a3), "r"(b0), "r"(b1))

// ---------------- device scratch (static: allocation-free rule) ---------------
__device__ float  g_zHi[(size_t)NQ];       // 64 MB: tf32-hi of z, [b][d][t]
__device__ float  g_zT[(size_t)NQ];        // 64 MB: exact fp32 z, [n][d]
__device__ float  g_dist[(size_t)NN*KK];   // 128 MB: approx dists
__device__ float  g_cbHi[KK * DD];         // 2 MB: tf32-hi codebook [k][d]
__device__ float  g_cbT[DD * KK];          // gather cache [d][k]
__device__ float  g_wsq[KK];
__device__ float  g_zsq[NN];
__device__ int    g_idx[NN];
__device__ int    g_wsqmax_bits;           // max wsq (float bits; atomicMax idempotent)
__device__ double g_loss;

// ---------------- K0a: codebook prep ------------------------------------------
__global__ void prep_codebook(const float* __restrict__ cb) {
    int k   = blockIdx.x;
    int tid = threadIdx.x;      // 128
    float s = 0.f;
    for (int d = tid; d < DD; d += 128) {
        float v = cb[(size_t)k * DD + d];
        g_cbT[(size_t)d * KK + k]  = v;
        g_cbHi[(size_t)k * DD + d] = __uint_as_float(to_tf32(v));
        s += v * v;
    }
    #pragma unroll
    for (int o = 16; o; o >>= 1) s += __shfl_xor_sync(0xffffffffu, s, o);
    __shared__ float ws[4];
    if ((tid & 31) == 0) ws[tid >> 5] = s;
    __syncthreads();
    if (tid == 0) {
        float w = (ws[0] + ws[1]) + (ws[2] + ws[3]);
        g_wsq[k] = w;
        atomicMax(&g_wsqmax_bits, __float_as_int(w));
        if (k == 0) g_loss = 0.0;
    }
}

// ---------------- K0b: z -> hi plane ([b][d][t]) + exact transposed ([n][d]) --
__global__ void transpose_split(const float* __restrict__ z) {
    __shared__ float tile[32][33];
    int b  = blockIdx.z;
    int d0 = blockIdx.y * 32;
    int t0 = blockIdx.x * 32;
    int tx = threadIdx.x, ty = threadIdx.y;
    #pragma unroll
    for (int i = ty; i < 32; i += 8) {
        size_t off = ((size_t)b * DD + d0 + i) * TT + t0 + tx;
        float v = z[off];
        g_zHi[off] = __uint_as_float(to_tf32(v));
        tile[i][tx] = v;
    }
    __syncthreads();
    #pragma unroll
    for (int i = ty; i < 32; i += 8)
        g_zT[(size_t)(b * TT + t0 + i) * DD + d0 + tx] = tile[tx][i];
}

// ---------------- K0c: per-row |z|^2 ------------------------------------------
__global__ void compute_zsq(const float* __restrict__ z) {
    int n0 = blockIdx.x * 128;
    int b  = n0 >> 11;
    int t  = (n0 & (TT - 1)) + threadIdx.x;
    const float* zb = z + (size_t)b * DD * TT + t;
    float s0 = 0.f, s1 = 0.f, s2 = 0.f, s3 = 0.f;
    #pragma unroll 4
    for (int d = 0; d < DD; d += 4) {
        float v0 = zb[(size_t)(d + 0) * TT];
        float v1 = zb[(size_t)(d + 1) * TT];
        float v2 = zb[(size_t)(d + 2) * TT];
        float v3 = zb[(size_t)(d + 3) * TT];
        s0 = fmaf(v0, v0, s0);
        s1 = fmaf(v1, v1, s1);
        s2 = fmaf(v2, v2, s2);
        s3 = fmaf(v3, v3, s3);
    }
    g_zsq[n0 + threadIdx.x] = (s0 + s1) + (s2 + s3);
}

// ---------------- K1: pass-1 TF32 hi-only GEMM -> dist matrix -----------------
__global__ __launch_bounds__(THREADS, 2)
void vq_pass1()
{
    extern __shared__ char dyn[];
    __shared__ float sWsq[KK];

    const uint32_t dynb = smem_u32(dyn);
    int tid  = threadIdx.x;
    int lane = tid & 31;
    int wid  = tid >> 5;
    int q    = lane & 3;
    int r4   = lane >> 2;
    int warpM  = (wid & 3) * 32;   // 4 M-bands of 32
    int warpNb = wid >> 2;         // 2 N-bands
    int warpN  = warpNb * 64;

    int n0 = blockIdx.x * M_TILE;  // grid = 256 (one wave at 2 CTAs/SM)
    int b  = n0 >> 11;
    int t0 = n0 & (TT - 1);
    size_t zoff = (size_t)b * DD * TT + t0;

    #pragma unroll
    for (int i = 0; i < 4; i++) sWsq[tid + i * 256] = g_wsq[tid + i * 256];

    float zsqr[4];   // rows warpM + 16mi + 8h + r4
    #pragma unroll
    for (int mi = 0; mi < 2; mi++)
        #pragma unroll
        for (int h = 0; h < 2; h++)
            zsqr[mi * 2 + h] = g_zsq[n0 + warpM + 16 * mi + 8 * h + r4];

    float acc[2][8][4];   // (mi, nf, e) = 64 floats
    #pragma unroll
    for (int mi = 0; mi < 2; mi++)
        #pragma unroll
        for (int nf = 0; nf < 8; nf++)
            #pragma unroll
            for (int e = 0; e < 4; e++) acc[mi][nf][e] = 0.f;

    // cp.async decomposition: per plane 1024 x16B chunks, 4/thread
    int aRow[4], aC[4], bN[4], bCd[4];
    #pragma unroll
    for (int i = 0; i < 4; i++) {
        int u = tid + i * 256;
        aRow[i] = u >> 5;          // 0..31  (d row)
        aC[i]   = u & 31;          // 16B chunk along m
        bN[i]   = u >> 3;          // 0..127 (n row)
        bCd[i]  = u & 7;           // 16B chunk along d
    }

    auto load_stage = [&](int gs, int buf) {
        int d0  = (gs & (STAGES_PER_NT - 1)) * D_STAGE;
        int kb0 = (gs >> 4) * N_TILE;
        uint32_t bb = dynb + buf * BUF_BYTES;
        #pragma unroll
        for (int i = 0; i < 4; i++) {
            CP_ASYNC16(bb + aRow[i] * (A_LD * 4) + aC[i] * 16,
                       g_zHi + zoff + (size_t)(d0 + aRow[i]) * TT + aC[i] * 4);
            CP_ASYNC16(bb + OFF_B + bN[i] * (B_LD * 4) + bCd[i] * 16,
                       g_cbHi + (size_t)(kb0 + bN[i]) * DD + d0 + bCd[i] * 4);
        }
        CP_COMMIT();
    };

    __syncthreads();   // sWsq ready
    load_stage(0, 0);

    #pragma unroll 1
    for (int gs = 0; gs < TOT_STAGES; gs++) {
        int cur = gs & 1;
        if (gs + 1 < TOT_STAGES) { load_stage(gs + 1, cur ^ 1); CP_WAIT1(); }
        else                     { CP_WAIT0(); }
        __syncthreads();   // stage gs visible

        const uint32_t* As = (const uint32_t*)(dyn + cur * BUF_BYTES);
        const uint32_t* Bs = (const uint32_t*)(dyn + cur * BUF_BYTES + OFF_B);

        #pragma unroll
        for (int j = 0; j < 4; j++) {
            uint32_t ah[2][4];
            #pragma unroll
            for (int mi = 0; mi < 2; mi++) {
                int rm = warpM + 16 * mi + r4;
                #pragma unroll
                for (int e = 0; e < 4; e++) {
                    int dd = 8 * j + q + (e >> 1) * 4;
                    int mm = rm + (e & 1) * 8;
                    ah[mi][e] = As[dd * A_LD + mm];
                }
            }
            #pragma unroll
            for (int nf = 0; nf < 8; nf++) {
                int nn = warpN + 8 * nf + r4;
                uint32_t b0 = Bs[nn * B_LD + 8 * j + q];
                uint32_t b1 = Bs[nn * B_LD + 8 * j + q + 4];
                #pragma unroll
                for (int mi = 0; mi < 2; mi++) {
                    float* c = acc[mi][nf];
                    MMA_TF32(c[0], c[1], c[2], c[3],
                             ah[mi][0], ah[mi][1], ah[mi][2], ah[mi][3], b0, b1);
                }
            }
        }

        // n-tile boundary: store dists, reset acc
        if ((gs & (STAGES_PER_NT - 1)) == STAGES_PER_NT - 1) {
            int kb0 = (gs >> 4) * N_TILE;
            #pragma unroll
            for (int mi = 0; mi < 2; mi++) {
                #pragma unroll
                for (int h = 0; h < 2; h++) {
                    int n = n0 + warpM + 16 * mi + 8 * h + r4;
                    float zs = zsqr[mi * 2 + h];
                    #pragma unroll
                    for (int nf = 0; nf < 8; nf++) {
                        int col = kb0 + warpN + 8 * nf + 2 * q;
                        float v0 = __fadd_rn(__fsub_rn(zs, __fmul_rn(2.0f, acc[mi][nf][2 * h + 0])), sWsq[col]);
                        float v1 = __fadd_rn(__fsub_rn(zs, __fmul_rn(2.0f, acc[mi][nf][2 * h + 1])), sWsq[col + 1]);
                        *(float2*)(g_dist + (size_t)n * KK + col) = make_float2(v0, v1);
                    }
                }
            }
            #pragma unroll
            for (int mi = 0; mi < 2; mi++)
                #pragma unroll
                for (int nf = 0; nf < 8; nf++)
                    #pragma unroll
                    for (int e = 0; e < 4; e++) acc[mi][nf][e] = 0.f;
        }
        __syncthreads();   // release buf cur
    }
}

// ---------------- K2: refine — exact argmin from candidates -------------------
__global__ __launch_bounds__(128)
void vq_refine(const float* __restrict__ cb, float* __restrict__ out) {
    int n   = blockIdx.x;
    int tid = threadIdx.x;
    int lane = tid & 31, wid = tid >> 5;
    const float* dr = g_dist + (size_t)n * KK;

    float4 da = ((const float4*)dr)[tid * 2];
    float4 db = ((const float4*)dr)[tid * 2 + 1];
    float d8[8] = { da.x, da.y, da.z, da.w, db.x, db.y, db.z, db.w };

    // local packed min (ascending k, strict < -> first index)
    ull best = ~0ull;
    #pragma unroll
    for (int i = 0; i < 8; i++) {
        ull p = ((ull)__float_as_uint(d8[i]) << 32) | (uint32_t)(tid * 8 + i);
        if (p < best) best = p;
    }
    #pragma unroll
    for (int o = 16; o; o >>= 1) {
        ull v = __shfl_xor_sync(0xffffffffu, best, o);
        if (v < best) best = v;
    }
    __shared__ ull sMin[4];
    if (lane == 0) sMin[wid] = best;
    __syncthreads();
    ull m01 = sMin[0] < sMin[1] ? sMin[0] : sMin[1];
    ull m23 = sMin[2] < sMin[3] ? sMin[2] : sMin[3];
    ull gmin = m01 < m23 ? m01 : m23;
    float minv = __uint_as_float((uint32_t)(gmin >> 32));

    float zsq = g_zsq[n];
    float wmaxsq = __int_as_float(g_wsqmax_bits);
    // per-entry bound (inflated): 2.5e-3 * ||z||*||w||max + 5e-4 ; margin = 2*bound
    float bound = fmaf(2.5e-3f, sqrtf(zsq * wmaxsq), 5.0e-4f);
    float thresh = minv + 2.0f * bound;

    __shared__ int sCnt, sOvf;
    __shared__ int sList[32];
    if (tid == 0) { sCnt = 0; sOvf = 0; }
    __syncthreads();
    #pragma unroll
    for (int i = 0; i < 8; i++) {
        if (d8[i] <= thresh) {
            int p = atomicAdd(&sCnt, 1);
            if (p < 32) sList[p] = tid * 8 + i; else sOvf = 1;
        }
    }
    __syncthreads();

    int winner;
    if (sCnt == 1 && !sOvf) {
        winner = (int)(uint32_t)(gmin & 0xffffffffULL);
    } else {
        __shared__ float sP[4];
        __shared__ ull   sBest;
        if (tid == 0) sBest = ~0ull;
        int m = sOvf ? KK : sCnt;
        const float* zr = g_zT + (size_t)n * DD;
        float4 zv0 = ((const float4*)zr)[tid];               // d = 4*tid .. +3
        for (int c = 0; c < m; c++) {
            int k = sOvf ? c : sList[c];
            const float* wr = cb + (size_t)k * DD;
            float4 wv = ((const float4*)wr)[tid];
            float s = 0.f;
            s = fmaf(zv0.x, wv.x, s);
            s = fmaf(zv0.y, wv.y, s);
            s = fmaf(zv0.z, wv.z, s);
            s = fmaf(zv0.w, wv.w, s);
            #pragma unroll
            for (int o = 16; o; o >>= 1) s += __shfl_xor_sync(0xffffffffu, s, o);
            if (lane == 0) sP[wid] = s;
            __syncthreads();
            if (tid == 0) {
                float S = (sP[0] + sP[1]) + (sP[2] + sP[3]);
                float dist = __fadd_rn(__fsub_rn(zsq, __fmul_rn(2.0f, S)), g_wsq[k]);
                ull p = ((ull)__float_as_uint(dist) << 32) | (uint32_t)k;
                if (p < sBest) sBest = p;
            }
            __syncthreads();
        }
        winner = (int)(uint32_t)(sBest & 0xffffffffULL);
    }

    if (tid == 0) {
        g_idx[n] = winner;
        out[(size_t)NQ + n] = (float)winner;
    }
}

// ---------------- K3: gather z_q, write z_q_st, loss (vectorized) -------------
__global__ void gather_out(const float* __restrict__ z, float* __restrict__ out) {
    int bd = blockIdx.x;
    int b  = bd >> 9;
    int d  = bd & (DD - 1);
    __shared__ float row[KK];
    ((float4*)row)[threadIdx.x] = ((const float4*)(g_cbT + (size_t)d * KK))[threadIdx.x];
    __syncthreads();

    size_t base = ((size_t)b * DD + d) * TT;
    int t = threadIdx.x * 8;
    int4  i0 = *(const int4*)(g_idx + b * TT + t);
    int4  i1 = *(const int4*)(g_idx + b * TT + t + 4);
    float4 z0 = *(const float4*)(z + base + t);
    float4 z1 = *(const float4*)(z + base + t + 4);

    float4 o0, o1;
    double lsum = 0.0;
    {
        float zq, df;
        zq = row[i0.x]; o0.x = __fadd_rn(z0.x, __fsub_rn(zq, z0.x)); df = __fsub_rn(zq, z0.x); lsum += (double)df * df;
        zq = row[i0.y]; o0.y = __fadd_rn(z0.y, __fsub_rn(zq, z0.y)); df = __fsub_rn(zq, z0.y); lsum += (double)df * df;
        zq = row[i0.z]; o0.z = __fadd_rn(z0.z, __fsub_rn(zq, z0.z)); df = __fsub_rn(zq, z0.z); lsum += (double)df * df;
        zq = row[i0.w]; o0.w = __fadd_rn(z0.w, __fsub_rn(zq, z0.w)); df = __fsub_rn(zq, z0.w); lsum += (double)df * df;
        zq = row[i1.x]; o1.x = __fadd_rn(z1.x, __fsub_rn(zq, z1.x)); df = __fsub_rn(zq, z1.x); lsum += (double)df * df;
        zq = row[i1.y]; o1.y = __fadd_rn(z1.y, __fsub_rn(zq, z1.y)); df = __fsub_rn(zq, z1.y); lsum += (double)df * df;
        zq = row[i1.z]; o1.z = __fadd_rn(z1.z, __fsub_rn(zq, z1.z)); df = __fsub_rn(zq, z1.z); lsum += (double)df * df;
        zq = row[i1.w]; o1.w = __fadd_rn(z1.w, __fsub_rn(zq, z1.w)); df = __fsub_rn(zq, z1.w); lsum += (double)df * df;
    }
    *(float4*)(out + base + t)     = o0;
    *(float4*)(out + base + t + 4) = o1;

    #pragma unroll
    for (int o = 16; o; o >>= 1) lsum += __shfl_xor_sync(0xffffffffu, lsum, o);
    __shared__ double red[8];
    if ((threadIdx.x & 31) == 0) red[threadIdx.x >> 5] = lsum;
    __syncthreads();
    if (threadIdx.x == 0) {
        double s = 0.0;
        #pragma unroll
        for (int i = 0; i < 8; i++) s += red[i];
        atomicAdd(&g_loss, s);
    }
}

// ---------------- K4: finalize loss ------------------------------------------
__global__ void finalize_loss(float* __restrict__ out) {
    out[(size_t)NQ + NN] = (float)(g_loss * (1.25 / (double)NQ));
}

// ---------------- launch ------------------------------------------------------
extern "C" void kernel_launch(void* const* d_in, const int* in_sizes, int n_in,
                              void* d_out, int out_size) {
    const float* z  = (const float*)d_in[0];   // [16, 512, 2048] fp32
    const float* cb = (const float*)d_in[1];   // [1024, 512] fp32
    float* out = (float*)d_out;                // [z_q_st | indices | loss]

    cudaFuncSetAttribute(vq_pass1, cudaFuncAttributeMaxDynamicSharedMemorySize, DYN_SMEM);

    prep_codebook<<<KK, 128>>>(cb);
    transpose_split<<<dim3(TT / 32, DD / 32, BB), dim3(32, 8)>>>(z);
    compute_zsq<<<NN / 128, 128>>>(z);
    vq_pass1<<<NN / M_TILE, THREADS, DYN_SMEM>>>();
    vq_refine<<<NN, 128>>>(cb, out);
    gather_out<<<BB * DD, 256>>>(z, out);
    finalize_loss<<<1, 1>>>(out);
}